// round 7
// baseline (speedup 1.0000x reference)
#include <cuda_runtime.h>
#include <cuda_fp16.h>
#include <math.h>
#include <float.h>
#include <stdint.h>

// ---------------- problem constants ----------------
#define TOKENS_TOTAL (32*2048)
#define IN_DIM   128
#define HID      64
#define OUT_DIM  64
#define CODEBOOK 2048

#define TB       128
#define NTHREADS 256
#define NBLOCKS  (TOKENS_TOTAL/TB)     // 512
#define XT_STRIDE 130
#define CCH      64                     // codes per staged chunk
#define NCH      (CODEBOOK/CCH)         // 32

// output layout: msg ++ idx(as float) ++ loss
#define MSG_ELEMS ((size_t)TOKENS_TOTAL*OUT_DIM)
#define IDX_OFF   MSG_ELEMS
#define LOSS_OFF  (MSG_ELEMS + TOKENS_TOTAL)

// ---------------- smem layout (word offsets; 1 word = 4B) ----------------
#define OFF_E2   0                      // 2048 f
#define OFF_XT   2048                   // 64 x 130 f -> end 10368
#define OFF_B    10368                  // 2 bufs x (hi 64x36) = 4608 w -> end 14976
#define B_ROW_W   36
#define B_TILE_W  (64*B_ROW_W)          // 2304
#define OFF_TBL  14976                  // 128 x u64 best-key table = 256 w
#define OFF_MARG 15232                  // 128 f per-token margins
#define OFF_Q    18560                  // queues: 8 warps x 2048 u16 = 4096 w -> end 26752
#define QCAP     2048
// MLP-phase overlays (dead during MLP / VQ respectively)
#define OFF_W    10368                  // weights (<= 8192 f) 10368..18560 (MLP only)
#define OFF_OBS  18560                  // obs tile / h2 (8192 f) 18560..26752 (MLP only)
#define OFF_H1   2048                   // h1 overlays XT (XT written later)
#define SMEM_FLOATS 26752               // 107008 B ; x2 CTAs fits 228KB

// packed codebook hi tiles: [2048 codes][32 fp16x2 words], word w = k-pair (2w,2w+1)
#define CBW 32
__device__ uint4 g_cbpack4[CODEBOOK * CBW / 4];   // 256 KB
__device__ float g_e2[CODEBOOK];
__device__ int   g_e2max_bits;          // max e2 as float bits (atomicMax, idempotent per replay)
__device__ float g_partial[NBLOCKS];

#define MARG_C (3.0f/512.0f)            // 3 * 2^-9 certified 1-term fp16 distance-error coeff

// ---------------- helpers ----------------
__device__ __forceinline__ uint32_t pack_h2(float x0, float x1) {
    __half2 hh = __floats2half2_rn(x0, x1);
    return *(uint32_t*)&hh;
}
__device__ __forceinline__ void mma16(float* c, const uint32_t* a, uint32_t b0, uint32_t b1) {
    asm volatile(
        "mma.sync.aligned.m16n8k16.row.col.f32.f16.f16.f32 "
        "{%0,%1,%2,%3}, {%4,%5,%6,%7}, {%8,%9}, {%0,%1,%2,%3};"
        : "+f"(c[0]), "+f"(c[1]), "+f"(c[2]), "+f"(c[3])
        : "r"(a[0]), "r"(a[1]), "r"(a[2]), "r"(a[3]), "r"(b0), "r"(b1));
}
__device__ __forceinline__ uint32_t fkey(float d) {
    uint32_t u = __float_as_uint(d);
    return (u & 0x80000000u) ? ~u : (u | 0x80000000u);   // order-preserving map
}

// packed fp32x2 (MLP)
__device__ __forceinline__ unsigned long long dup2(float x) {
    unsigned long long r; asm("mov.b64 %0, {%1, %1};" : "=l"(r) : "f"(x)); return r;
}
__device__ __forceinline__ void ffma2(unsigned long long& d, unsigned long long a, unsigned long long b) {
    asm("fma.rn.f32x2 %0, %1, %2, %0;" : "+l"(d) : "l"(a), "l"(b));
}
__device__ __forceinline__ float lo32(unsigned long long v) { return __uint_as_float((unsigned)v); }
__device__ __forceinline__ float hi32(unsigned long long v) { return __uint_as_float((unsigned)(v >> 32)); }

// ---------------- MLP layer (proven rounds 1..6) ----------------
template<int KD, int NT, int OUTMODE, bool RELU>
__device__ __forceinline__ void mlp_layer(const float* in_s, int in_stride,
                                          const float* w_s, const float* __restrict__ b_g,
                                          float* out_s, int tid)
{
    const int jg = tid & 7;
    const int tg = tid >> 3;
    float bj[4][2];
#pragma unroll
    for (int jj = 0; jj < 4; jj++) {
        int j0 = jg*2 + 16*jj;
        bj[jj][0] = __ldg(b_g + j0);
        bj[jj][1] = __ldg(b_g + j0 + 1);
    }
    unsigned long long acc[NT][4];
#pragma unroll
    for (int it = 0; it < NT; it++)
#pragma unroll
        for (int jj = 0; jj < 4; jj++) acc[it][jj] = 0ULL;

#pragma unroll 4
    for (int k0 = 0; k0 < KD; k0 += 4) {
        float xin[NT][4];
#pragma unroll
        for (int it = 0; it < NT; it++) {
            float4 v = *(const float4*)(in_s + (tg*NT + it)*in_stride + k0);
            xin[it][0] = v.x; xin[it][1] = v.y; xin[it][2] = v.z; xin[it][3] = v.w;
        }
#pragma unroll
        for (int kk = 0; kk < 4; kk++) {
            unsigned long long wp[4];
#pragma unroll
            for (int jj = 0; jj < 4; jj++)
                wp[jj] = *(const unsigned long long*)(w_s + (k0+kk)*64 + jg*2 + 16*jj);
#pragma unroll
            for (int it = 0; it < NT; it++) {
                unsigned long long xd = dup2(xin[it][kk]);
#pragma unroll
                for (int jj = 0; jj < 4; jj++) ffma2(acc[it][jj], xd, wp[jj]);
            }
        }
    }
#pragma unroll
    for (int it = 0; it < NT; it++) {
        int t = tg*NT + it;
#pragma unroll
        for (int jj = 0; jj < 4; jj++) {
            int j0 = jg*2 + 16*jj;
            float v0 = lo32(acc[it][jj]) + bj[jj][0];
            float v1 = hi32(acc[it][jj]) + bj[jj][1];
            if (RELU) { v0 = fmaxf(v0, 0.0f); v1 = fmaxf(v1, 0.0f); }
            if (OUTMODE == 0) {
                out_s[t*64 + j0]     = v0;
                out_s[t*64 + j0 + 1] = v1;
            } else {
                out_s[j0*XT_STRIDE + t]       = v0;
                out_s[(j0 + 1)*XT_STRIDE + t] = v1;
            }
        }
    }
}

// ---------------- prep: hi-fp16 codebook pack + exact e2 + max e2 ----------------
__global__ void prep_kernel(const float* __restrict__ cb) {
    int gt = blockIdx.x * 256 + threadIdx.x;
    int c  = gt >> 2;
    int q  = gt & 3;
    if (c >= CODEBOOK) return;

    uint32_t hw[8];
    float sq = 0.0f;
#pragma unroll
    for (int i = 0; i < 4; i++) {
        float4 f = *(const float4*)(cb + (size_t)c*OUT_DIM + q*16 + i*4);
        hw[i*2]   = pack_h2(f.x, f.y);
        hw[i*2+1] = pack_h2(f.z, f.w);
        sq += f.x*f.x + f.y*f.y + f.z*f.z + f.w*f.w;
    }
    uint32_t* hrow = (uint32_t*)g_cbpack4 + c*CBW + q*8;
    *(uint4*)(hrow)     = make_uint4(hw[0], hw[1], hw[2], hw[3]);
    *(uint4*)(hrow + 4) = make_uint4(hw[4], hw[5], hw[6], hw[7]);

    sq += __shfl_xor_sync(0xffffffffu, sq, 1);
    sq += __shfl_xor_sync(0xffffffffu, sq, 2);
    if (q == 0) {
        g_e2[c] = sq;
        atomicMax(&g_e2max_bits, __float_as_int(sq));  // sq > 0: int compare valid; idempotent per replay
    }
}

// ---------------- exact fp32 rescore: d = e2 - 2 * x.e ----------------
__device__ __forceinline__ float rescore(const float* __restrict__ cb, const float* xsT,
                                          const float* e2s, int t, int c) {
    const float4* er = (const float4*)(cb + (size_t)c * OUT_DIM);
    float s = 0.0f;
#pragma unroll
    for (int j4 = 0; j4 < 16; j4++) {
        float4 e4 = __ldg(er + j4);
        int j = j4*4;
        s = fmaf(e4.x, xsT[(j  )*XT_STRIDE + t], s);
        s = fmaf(e4.y, xsT[(j+1)*XT_STRIDE + t], s);
        s = fmaf(e4.z, xsT[(j+2)*XT_STRIDE + t], s);
        s = fmaf(e4.w, xsT[(j+3)*XT_STRIDE + t], s);
    }
    return fmaf(-2.0f, s, e2s[c]);
}

// ---------------- fused kernel ----------------
__global__ void __launch_bounds__(NTHREADS, 2)
vq_main(const float* __restrict__ obs,
        const float* __restrict__ W1, const float* __restrict__ b1,
        const float* __restrict__ W2, const float* __restrict__ b2,
        const float* __restrict__ W3, const float* __restrict__ b3,
        const float* __restrict__ cb,
        float* __restrict__ out)
{
    extern __shared__ float sm[];
    __shared__ int wq_cnt[8];
    const int tid  = threadIdx.x;
    const int wid  = tid >> 5;
    const int lane = tid & 31;
    const int r    = lane >> 2;      // 0..7
    const int q    = lane & 3;       // 0..3
    const int tok0 = blockIdx.x * TB;

    // e2 table -> smem
    for (int i = tid; i < CODEBOOK; i += NTHREADS) sm[OFF_E2 + i] = g_e2[i];

    // ================= MLP (FFMA2, bit-identical to rounds 1/3/4/6) =================
    {
        const float4* w4 = (const float4*)W1;
        float4* d4 = (float4*)(sm + OFF_W);
        for (int i = tid; i < (IN_DIM*HID)/4; i += NTHREADS) d4[i] = w4[i];
    }
    for (int half = 0; half < 2; half++) {
        __syncthreads();
        const float4* o4 = (const float4*)(obs + (size_t)(tok0 + half*64) * IN_DIM);
        float4* d4 = (float4*)(sm + OFF_OBS);
        for (int i = tid; i < (64*IN_DIM)/4; i += NTHREADS) d4[i] = o4[i];
        __syncthreads();
        mlp_layer<IN_DIM, 2, 0, true>(sm + OFF_OBS, IN_DIM, sm + OFF_W, b1,
                                      sm + OFF_H1 + half*64*HID, tid);
    }
    __syncthreads();
    {
        const float4* w4 = (const float4*)W2;
        float4* d4 = (float4*)(sm + OFF_W);
        for (int i = tid; i < (HID*HID)/4; i += NTHREADS) d4[i] = w4[i];
    }
    __syncthreads();
    mlp_layer<HID, 4, 0, true>(sm + OFF_H1, HID, sm + OFF_W, b2, sm + OFF_OBS, tid);
    __syncthreads();
    {
        const float4* w4 = (const float4*)W3;
        float4* d4 = (float4*)(sm + OFF_W);
        for (int i = tid; i < (HID*OUT_DIM)/4; i += NTHREADS) d4[i] = w4[i];
    }
    __syncthreads();
    mlp_layer<HID, 4, 1, false>(sm + OFF_OBS, HID, sm + OFF_W, b3, sm + OFF_XT, tid);
    __syncthreads();

    const float* xsT = sm + OFF_XT;
    const float* e2s = sm + OFF_E2;
    const int tokw = wid * 16;

    // ---- post-MLP init: best-key table, margins, queue counters ----
    unsigned long long* tbl = (unsigned long long*)(sm + OFF_TBL);
    float* margS = sm + OFF_MARG;
    if (tid < TB) {
        tbl[tid] = 0xFFFFFFFFFFFFFFFFull;
        float s = 0.0f;
#pragma unroll
        for (int j = 0; j < OUT_DIM; j++) {
            float xv = xsT[j*XT_STRIDE + tid];
            s = fmaf(xv, xv, s);
        }
        float emax = sqrtf(__int_as_float(g_e2max_bits));
        margS[tid] = MARG_C * sqrtf(s) * emax + 1e-4f;   // certified + subnormal slack
    }
    if (tid < 8) wq_cnt[tid] = 0;

    // ---- A fragments (m16 x k64, fp16 hi) ----
    uint32_t Ah[4][4];
#pragma unroll
    for (int kb = 0; kb < 4; kb++) {
        int k0 = kb*16;
        const float* x0 = xsT + tokw;
        Ah[kb][0] = pack_h2(x0[(k0 + 2*q    )*XT_STRIDE + r],
                            x0[(k0 + 2*q + 1)*XT_STRIDE + r]);
        Ah[kb][1] = pack_h2(x0[(k0 + 2*q    )*XT_STRIDE + r + 8],
                            x0[(k0 + 2*q + 1)*XT_STRIDE + r + 8]);
        Ah[kb][2] = pack_h2(x0[(k0 + 2*q + 8)*XT_STRIDE + r],
                            x0[(k0 + 2*q + 9)*XT_STRIDE + r]);
        Ah[kb][3] = pack_h2(x0[(k0 + 2*q + 8)*XT_STRIDE + r + 8],
                            x0[(k0 + 2*q + 9)*XT_STRIDE + r + 8]);
    }

    // ---- stage chunk 0 ----
    uint32_t* bw = (uint32_t*)(sm + OFF_B);
    {
        const uint4* hb = g_cbpack4;
        uint4 v0 = __ldg(hb + tid), v1 = __ldg(hb + tid + 256);
        int c0 = tid >> 3, w0 = (tid & 7)*4;
        *(uint4*)(bw + c0*B_ROW_W + w0)             = v0;
        *(uint4*)(bw + (c0+32)*B_ROW_W + w0)        = v1;
    }
    __syncthreads();   // also publishes tbl/margS/wq_cnt

    uint16_t* wq = (uint16_t*)(sm + OFF_Q) + wid*QCAP;
    float marg0 = margS[tokw + r];
    float marg1 = margS[tokw + r + 8];
    float rbm0 = FLT_MAX, rbm1 = FLT_MAX;   // (min seen d1) + marg

    // ================= VQ sweep: 1-term fp16 mma + certified candidate enqueue =================
    for (int ch = 0; ch < NCH; ch++) {
        const int buf = ch & 1;
        uint4 v0, v1;
        const bool more = (ch + 1 < NCH);
        if (more) {
            const uint4* hb = g_cbpack4 + (size_t)(ch+1)*CCH*(CBW/4);
            v0 = __ldg(hb + tid); v1 = __ldg(hb + tid + 256);
        }

        const uint32_t* bh = bw + buf*B_TILE_W*2/2 * 0 + buf*B_TILE_W;   // buf*B_TILE_W
#pragma unroll
        for (int grp = 0; grp < 2; grp++) {
            float accM[4][4];
#pragma unroll
            for (int g = 0; g < 4; g++)
#pragma unroll
                for (int j = 0; j < 4; j++) accM[g][j] = 0.f;

            int rb0 = (grp*32 +  0 + r)*B_ROW_W + q;
            int rb1 = (grp*32 +  8 + r)*B_ROW_W + q;
            int rb2 = (grp*32 + 16 + r)*B_ROW_W + q;
            int rb3 = (grp*32 + 24 + r)*B_ROW_W + q;

#pragma unroll
            for (int kb = 0; kb < 4; kb++) {
                int ko = kb*8;
                uint32_t b0[4], b1[4];
                b0[0] = bh[rb0 + ko]; b1[0] = bh[rb0 + ko + 4];
                b0[1] = bh[rb1 + ko]; b1[1] = bh[rb1 + ko + 4];
                b0[2] = bh[rb2 + ko]; b1[2] = bh[rb2 + ko + 4];
                b0[3] = bh[rb3 + ko]; b1[3] = bh[rb3 + ko + 4];
#pragma unroll
                for (int g = 0; g < 4; g++) mma16(accM[g], Ah[kb], b0[g], b1[g]);
            }

            // epilogue: approx dist, enqueue candidates within certified margin
#pragma unroll
            for (int g = 0; g < 4; g++) {
                int code0 = ch*CCH + grp*32 + g*8 + 2*q;
                float e20 = e2s[code0];
                float e21 = e2s[code0 + 1];
                float d0 = fmaf(-2.0f, accM[g][0], e20);
                float d1 = fmaf(-2.0f, accM[g][1], e21);
                float d2 = fmaf(-2.0f, accM[g][2], e20);
                float d3 = fmaf(-2.0f, accM[g][3], e21);
                if (d0 < rbm0) {
                    int p = atomicAdd(&wq_cnt[wid], 1);
                    if (p < QCAP) wq[p] = (uint16_t)((r << 11) | code0);
                    rbm0 = fminf(rbm0, d0 + marg0);
                }
                if (d1 < rbm0) {
                    int p = atomicAdd(&wq_cnt[wid], 1);
                    if (p < QCAP) wq[p] = (uint16_t)((r << 11) | (code0 + 1));
                    rbm0 = fminf(rbm0, d1 + marg0);
                }
                if (d2 < rbm1) {
                    int p = atomicAdd(&wq_cnt[wid], 1);
                    if (p < QCAP) wq[p] = (uint16_t)(((r + 8) << 11) | code0);
                    rbm1 = fminf(rbm1, d2 + marg1);
                }
                if (d3 < rbm1) {
                    int p = atomicAdd(&wq_cnt[wid], 1);
                    if (p < QCAP) wq[p] = (uint16_t)(((r + 8) << 11) | (code0 + 1));
                    rbm1 = fminf(rbm1, d3 + marg1);
                }
            }
        }

        // share running bounds across the 4 q-lanes of each token (tighter -> fewer pushes)
        rbm0 = fminf(rbm0, __shfl_xor_sync(0xffffffffu, rbm0, 1));
        rbm0 = fminf(rbm0, __shfl_xor_sync(0xffffffffu, rbm0, 2));
        rbm1 = fminf(rbm1, __shfl_xor_sync(0xffffffffu, rbm1, 1));
        rbm1 = fminf(rbm1, __shfl_xor_sync(0xffffffffu, rbm1, 2));

        __syncthreads();
        if (more) {
            int c0 = tid >> 3, w0 = (tid & 7)*4;
            uint32_t* dst = bw + (1 - buf)*B_TILE_W;
            *(uint4*)(dst + c0*B_ROW_W + w0)      = v0;
            *(uint4*)(dst + (c0+32)*B_ROW_W + w0) = v1;
        }
        __syncthreads();
    }

    // ================= exact rescore of candidates =================
    __syncwarp();
    int nq = wq_cnt[wid];
    int n  = nq < QCAP ? nq : QCAP;
    for (int i = lane; i < n; i += 32) {
        uint16_t e = wq[i];
        int slot = e >> 11, c = e & 0x7FF;
        int t = tokw + slot;
        float d = rescore(cb, xsT, e2s, t, c);
        unsigned long long key = ((unsigned long long)fkey(d) << 32) | (unsigned)c;
        atomicMin(&tbl[t], key);
    }
    if (nq > QCAP) {   // overflow: exhaustive exact fallback (correctness guarantee; ~never taken)
        for (int s = 0; s < 16; s++) {
            int t = tokw + s;
            for (int c = lane; c < CODEBOOK; c += 32) {
                float d = rescore(cb, xsT, e2s, t, c);
                unsigned long long key = ((unsigned long long)fkey(d) << 32) | (unsigned)c;
                atomicMin(&tbl[t], key);
            }
        }
    }
    __syncthreads();

    // ---- idx write ----
    if (tid < TB) {
        int bc = (int)(tbl[tid] & 0xFFFFFFFFull);
        out[IDX_OFF + (size_t)(tok0 + tid)] = (float)bc;
    }
    __syncthreads();

    // ---- msg write + commitment-loss partial (exact fp32 x) ----
    float part = 0.0f;
    for (int f = tid; f < TB*OUT_DIM; f += NTHREADS) {
        int t = f >> 6, j = f & 63;
        int c = (int)(tbl[t] & 0xFFFFFFFFull);
        float qv = __ldg(cb + (size_t)c * OUT_DIM + j);
        float xv = xsT[j*XT_STRIDE + t];
        out[(size_t)(tok0 + t)*OUT_DIM + j] = xv + (qv - xv);
        float dd = qv - xv;
        part += dd * dd;
    }
#pragma unroll
    for (int o = 16; o > 0; o >>= 1)
        part += __shfl_down_sync(0xffffffffu, part, o);
    __shared__ float swred[8];
    if ((tid & 31) == 0) swred[tid >> 5] = part;
    __syncthreads();
    if (tid == 0) {
        float s = 0.0f;
#pragma unroll
        for (int w = 0; w < 8; w++) s += swred[w];
        g_partial[blockIdx.x] = s;
    }
}

// ---------------- deterministic loss reduction ----------------
__global__ void loss_reduce(float* __restrict__ out) {
    __shared__ float s[NBLOCKS];
    int t = threadIdx.x;
    s[t] = g_partial[t];
    __syncthreads();
    for (int o = NBLOCKS/2; o > 0; o >>= 1) {
        if (t < o) s[t] += s[t + o];
        __syncthreads();
    }
    if (t == 0) out[LOSS_OFF] = s[0] * (1.0f / (float)MSG_ELEMS);
}

extern "C" void kernel_launch(void* const* d_in, const int* in_sizes, int n_in,
                              void* d_out, int out_size)
{
    const float* obs = (const float*)d_in[0];
    const float* W1  = (const float*)d_in[1];
    const float* b1  = (const float*)d_in[2];
    const float* W2  = (const float*)d_in[3];
    const float* b2  = (const float*)d_in[4];
    const float* W3  = (const float*)d_in[5];
    const float* b3  = (const float*)d_in[6];
    const float* cb  = (const float*)d_in[7];
    float* out = (float*)d_out;

    cudaFuncSetAttribute(vq_main, cudaFuncAttributeMaxDynamicSharedMemorySize,
                         SMEM_FLOATS * (int)sizeof(float));

    prep_kernel<<<(CODEBOOK*4 + 255)/256, 256>>>(cb);
    vq_main<<<NBLOCKS, NTHREADS, SMEM_FLOATS * sizeof(float)>>>(
        obs, W1, b1, W2, b2, W3, b3, cb, out);
    loss_reduce<<<1, NBLOCKS>>>(out);
}

// round 9
// speedup vs baseline: 1.0070x; 1.0070x over previous
#include <cuda_runtime.h>
#include <cuda_fp16.h>
#include <math.h>
#include <float.h>
#include <stdint.h>

// ---------------- problem constants ----------------
#define TOKENS_TOTAL (32*2048)
#define IN_DIM   128
#define HID      64
#define OUT_DIM  64
#define CODEBOOK 2048

#define TB       128
#define NTHREADS 256
#define NBLOCKS  (TOKENS_TOTAL/TB)     // 512
#define XT_STRIDE 130
#define CCH      128                    // codes per staged chunk
#define NCH      (CODEBOOK/CCH)         // 16

// output layout: msg ++ idx(as float) ++ loss
#define MSG_ELEMS ((size_t)TOKENS_TOTAL*OUT_DIM)
#define IDX_OFF   MSG_ELEMS
#define LOSS_OFF  (MSG_ELEMS + TOKENS_TOTAL)

// ---------------- smem layout (word offsets; 1 word = 4B) ----------------
#define OFF_E2   0                      // 2048 f
#define OFF_XT   2048                   // 64 x 130 f -> end 10368
#define OFF_B    10368                  // 2 bufs x (hi 128x36) = 9216 w -> end 19584
#define B_ROW_W   36
#define B_TILE_W  (CCH*B_ROW_W)         // 4608
#define OFF_TBL  19584                  // 128 x u64 = 256 w -> 19840
#define OFF_MARG 19840                  // 128 f -> 19968
#define OFF_Q    19968                  // queues: 8 warps x 1024 u16 = 4096 w -> 24064 (< 26752 OK)
#define QCAP     1024
// MLP-phase overlays (dead during MLP / VQ respectively)
#define OFF_W    10368                  // weights (<= 8192 f), MLP only
#define OFF_OBS  18560                  // obs tile / h2 (8192 f), MLP only
#define OFF_H1   2048                   // h1 overlays XT (XT written later)
#define SMEM_FLOATS 26752               // 107008 B ; x2 CTAs fits

// packed codebook hi tiles: [2048 codes][32 fp16x2 words], word w = k-pair (2w,2w+1)
#define CBW 32
__device__ uint4 g_cbpack4[CODEBOOK * CBW / 4];   // 256 KB
__device__ float g_e2[CODEBOOK];
__device__ int   g_e2max_bits;
__device__ float g_partial[NBLOCKS];

#define MARG_C (3.0f/512.0f)            // 3 * 2^-9 certified 1-term fp16 distance-error coeff

// ---------------- helpers ----------------
__device__ __forceinline__ uint32_t pack_h2(float x0, float x1) {
    __half2 hh = __floats2half2_rn(x0, x1);
    return *(uint32_t*)&hh;
}
__device__ __forceinline__ void mma16(float* c, const uint32_t* a, uint32_t b0, uint32_t b1) {
    asm volatile(
        "mma.sync.aligned.m16n8k16.row.col.f32.f16.f16.f32 "
        "{%0,%1,%2,%3}, {%4,%5,%6,%7}, {%8,%9}, {%0,%1,%2,%3};"
        : "+f"(c[0]), "+f"(c[1]), "+f"(c[2]), "+f"(c[3])
        : "r"(a[0]), "r"(a[1]), "r"(a[2]), "r"(a[3]), "r"(b0), "r"(b1));
}
__device__ __forceinline__ uint32_t fkey(float d) {
    uint32_t u = __float_as_uint(d);
    return (u & 0x80000000u) ? ~u : (u | 0x80000000u);
}

// packed fp32x2 (MLP)
__device__ __forceinline__ unsigned long long dup2(float x) {
    unsigned long long r; asm("mov.b64 %0, {%1, %1};" : "=l"(r) : "f"(x)); return r;
}
__device__ __forceinline__ void ffma2(unsigned long long& d, unsigned long long a, unsigned long long b) {
    asm("fma.rn.f32x2 %0, %1, %2, %0;" : "+l"(d) : "l"(a), "l"(b));
}
__device__ __forceinline__ float lo32(unsigned long long v) { return __uint_as_float((unsigned)v); }
__device__ __forceinline__ float hi32(unsigned long long v) { return __uint_as_float((unsigned)(v >> 32)); }

// ---------------- MLP layer (proven rounds 1..7) ----------------
template<int KD, int NT, int OUTMODE, bool RELU>
__device__ __forceinline__ void mlp_layer(const float* in_s, int in_stride,
                                          const float* w_s, const float* __restrict__ b_g,
                                          float* out_s, int tid)
{
    const int jg = tid & 7;
    const int tg = tid >> 3;
    float bj[4][2];
#pragma unroll
    for (int jj = 0; jj < 4; jj++) {
        int j0 = jg*2 + 16*jj;
        bj[jj][0] = __ldg(b_g + j0);
        bj[jj][1] = __ldg(b_g + j0 + 1);
    }
    unsigned long long acc[NT][4];
#pragma unroll
    for (int it = 0; it < NT; it++)
#pragma unroll
        for (int jj = 0; jj < 4; jj++) acc[it][jj] = 0ULL;

#pragma unroll 4
    for (int k0 = 0; k0 < KD; k0 += 4) {
        float xin[NT][4];
#pragma unroll
        for (int it = 0; it < NT; it++) {
            float4 v = *(const float4*)(in_s + (tg*NT + it)*in_stride + k0);
            xin[it][0] = v.x; xin[it][1] = v.y; xin[it][2] = v.z; xin[it][3] = v.w;
        }
#pragma unroll
        for (int kk = 0; kk < 4; kk++) {
            unsigned long long wp[4];
#pragma unroll
            for (int jj = 0; jj < 4; jj++)
                wp[jj] = *(const unsigned long long*)(w_s + (k0+kk)*64 + jg*2 + 16*jj);
#pragma unroll
            for (int it = 0; it < NT; it++) {
                unsigned long long xd = dup2(xin[it][kk]);
#pragma unroll
                for (int jj = 0; jj < 4; jj++) ffma2(acc[it][jj], xd, wp[jj]);
            }
        }
    }
#pragma unroll
    for (int it = 0; it < NT; it++) {
        int t = tg*NT + it;
#pragma unroll
        for (int jj = 0; jj < 4; jj++) {
            int j0 = jg*2 + 16*jj;
            float v0 = lo32(acc[it][jj]) + bj[jj][0];
            float v1 = hi32(acc[it][jj]) + bj[jj][1];
            if (RELU) { v0 = fmaxf(v0, 0.0f); v1 = fmaxf(v1, 0.0f); }
            if (OUTMODE == 0) {
                out_s[t*64 + j0]     = v0;
                out_s[t*64 + j0 + 1] = v1;
            } else {
                out_s[j0*XT_STRIDE + t]       = v0;
                out_s[(j0 + 1)*XT_STRIDE + t] = v1;
            }
        }
    }
}

// ---------------- prep: hi-fp16 codebook pack + exact e2 + max e2 ----------------
__global__ void prep_kernel(const float* __restrict__ cb) {
    int gt = blockIdx.x * 256 + threadIdx.x;
    int c  = gt >> 2;
    int q  = gt & 3;
    if (c >= CODEBOOK) return;

    uint32_t hw[8];
    float sq = 0.0f;
#pragma unroll
    for (int i = 0; i < 4; i++) {
        float4 f = *(const float4*)(cb + (size_t)c*OUT_DIM + q*16 + i*4);
        hw[i*2]   = pack_h2(f.x, f.y);
        hw[i*2+1] = pack_h2(f.z, f.w);
        sq += f.x*f.x + f.y*f.y + f.z*f.z + f.w*f.w;
    }
    uint32_t* hrow = (uint32_t*)g_cbpack4 + c*CBW + q*8;
    *(uint4*)(hrow)     = make_uint4(hw[0], hw[1], hw[2], hw[3]);
    *(uint4*)(hrow + 4) = make_uint4(hw[4], hw[5], hw[6], hw[7]);

    sq += __shfl_xor_sync(0xffffffffu, sq, 1);
    sq += __shfl_xor_sync(0xffffffffu, sq, 2);
    if (q == 0) {
        g_e2[c] = sq;
        atomicMax(&g_e2max_bits, __float_as_int(sq));
    }
}

// ---------------- exact fp32 rescore: d = e2 - 2 * x.e ----------------
__device__ __forceinline__ float rescore(const float* __restrict__ cb, const float* xsT,
                                          const float* e2s, int t, int c) {
    const float4* er = (const float4*)(cb + (size_t)c * OUT_DIM);
    float s = 0.0f;
#pragma unroll
    for (int j4 = 0; j4 < 16; j4++) {
        float4 e4 = __ldg(er + j4);
        int j = j4*4;
        s = fmaf(e4.x, xsT[(j  )*XT_STRIDE + t], s);
        s = fmaf(e4.y, xsT[(j+1)*XT_STRIDE + t], s);
        s = fmaf(e4.z, xsT[(j+2)*XT_STRIDE + t], s);
        s = fmaf(e4.w, xsT[(j+3)*XT_STRIDE + t], s);
    }
    return fmaf(-2.0f, s, e2s[c]);
}

// ---------------- fused kernel ----------------
__global__ void __launch_bounds__(NTHREADS, 2)
vq_main(const float* __restrict__ obs,
        const float* __restrict__ W1, const float* __restrict__ b1,
        const float* __restrict__ W2, const float* __restrict__ b2,
        const float* __restrict__ W3, const float* __restrict__ b3,
        const float* __restrict__ cb,
        float* __restrict__ out)
{
    extern __shared__ float sm[];
    __shared__ int wq_cnt[8];
    const int tid  = threadIdx.x;
    const int wid  = tid >> 5;
    const int lane = tid & 31;
    const int r    = lane >> 2;      // 0..7
    const int q    = lane & 3;       // 0..3
    const int tok0 = blockIdx.x * TB;

    for (int i = tid; i < CODEBOOK; i += NTHREADS) sm[OFF_E2 + i] = g_e2[i];

    // ================= MLP (FFMA2, bit-identical to prior rounds) =================
    {
        const float4* w4 = (const float4*)W1;
        float4* d4 = (float4*)(sm + OFF_W);
        for (int i = tid; i < (IN_DIM*HID)/4; i += NTHREADS) d4[i] = w4[i];
    }
    for (int half = 0; half < 2; half++) {
        __syncthreads();
        const float4* o4 = (const float4*)(obs + (size_t)(tok0 + half*64) * IN_DIM);
        float4* d4 = (float4*)(sm + OFF_OBS);
        for (int i = tid; i < (64*IN_DIM)/4; i += NTHREADS) d4[i] = o4[i];
        __syncthreads();
        mlp_layer<IN_DIM, 2, 0, true>(sm + OFF_OBS, IN_DIM, sm + OFF_W, b1,
                                      sm + OFF_H1 + half*64*HID, tid);
    }
    __syncthreads();
    {
        const float4* w4 = (const float4*)W2;
        float4* d4 = (float4*)(sm + OFF_W);
        for (int i = tid; i < (HID*HID)/4; i += NTHREADS) d4[i] = w4[i];
    }
    __syncthreads();
    mlp_layer<HID, 4, 0, true>(sm + OFF_H1, HID, sm + OFF_W, b2, sm + OFF_OBS, tid);
    __syncthreads();
    {
        const float4* w4 = (const float4*)W3;
        float4* d4 = (float4*)(sm + OFF_W);
        for (int i = tid; i < (HID*OUT_DIM)/4; i += NTHREADS) d4[i] = w4[i];
    }
    __syncthreads();
    mlp_layer<HID, 4, 1, false>(sm + OFF_OBS, HID, sm + OFF_W, b3, sm + OFF_XT, tid);
    __syncthreads();

    const float* xsT = sm + OFF_XT;
    const float* e2s = sm + OFF_E2;
    const int tokw = wid * 16;

    // ---- post-MLP init: best-key table, margins, queue counters ----
    unsigned long long* tbl = (unsigned long long*)(sm + OFF_TBL);
    float* margS = sm + OFF_MARG;
    if (tid < TB) {
        tbl[tid] = 0xFFFFFFFFFFFFFFFFull;
        float s = 0.0f;
#pragma unroll
        for (int j = 0; j < OUT_DIM; j++) {
            float xv = xsT[j*XT_STRIDE + tid];
            s = fmaf(xv, xv, s);
        }
        float emax = sqrtf(__int_as_float(g_e2max_bits));
        margS[tid] = MARG_C * sqrtf(s) * emax + 1e-4f;
    }
    if (tid < 8) wq_cnt[tid] = 0;

    // ---- A fragments (m16 x k64, fp16 hi) ----
    uint32_t Ah[4][4];
#pragma unroll
    for (int kb = 0; kb < 4; kb++) {
        int k0 = kb*16;
        const float* x0 = xsT + tokw;
        Ah[kb][0] = pack_h2(x0[(k0 + 2*q    )*XT_STRIDE + r],
                            x0[(k0 + 2*q + 1)*XT_STRIDE + r]);
        Ah[kb][1] = pack_h2(x0[(k0 + 2*q    )*XT_STRIDE + r + 8],
                            x0[(k0 + 2*q + 1)*XT_STRIDE + r + 8]);
        Ah[kb][2] = pack_h2(x0[(k0 + 2*q + 8)*XT_STRIDE + r],
                            x0[(k0 + 2*q + 9)*XT_STRIDE + r]);
        Ah[kb][3] = pack_h2(x0[(k0 + 2*q + 8)*XT_STRIDE + r + 8],
                            x0[(k0 + 2*q + 9)*XT_STRIDE + r + 8]);
    }

    // ---- stage chunk 0 (128 codes = 1024 uint4; 4 per thread) ----
    uint32_t* bw = (uint32_t*)(sm + OFF_B);
    {
        const uint4* hb = g_cbpack4;
#pragma unroll
        for (int i = 0; i < 4; i++) {
            uint4 v = __ldg(hb + tid + i*256);
            int idx = tid + i*256;
            int c0 = idx >> 3, w0 = (idx & 7)*4;
            *(uint4*)(bw + c0*B_ROW_W + w0) = v;
        }
    }
    __syncthreads();   // publishes tbl/margS/wq_cnt + chunk 0

    uint16_t* wq = (uint16_t*)(sm + OFF_Q) + wid*QCAP;
    float marg0 = margS[tokw + r];
    float marg1 = margS[tokw + r + 8];
    float rbm0 = FLT_MAX, rbm1 = FLT_MAX;

    // ================= VQ sweep: 1-term fp16 mma + ballot-gated candidate enqueue =================
    for (int ch = 0; ch < NCH; ch++) {
        const int buf = ch & 1;
        uint4 pv[4];
        const bool more = (ch + 1 < NCH);
        if (more) {
            const uint4* hb = g_cbpack4 + (size_t)(ch+1)*CCH*(CBW/4);
#pragma unroll
            for (int i = 0; i < 4; i++) pv[i] = __ldg(hb + tid + i*256);
        }

        const uint32_t* bh = bw + buf*B_TILE_W;
#pragma unroll
        for (int grp = 0; grp < 4; grp++) {
            float accM[4][4];
#pragma unroll
            for (int g = 0; g < 4; g++)
#pragma unroll
                for (int j = 0; j < 4; j++) accM[g][j] = 0.f;

            int rb0 = (grp*32 +  0 + r)*B_ROW_W + q;
            int rb1 = (grp*32 +  8 + r)*B_ROW_W + q;
            int rb2 = (grp*32 + 16 + r)*B_ROW_W + q;
            int rb3 = (grp*32 + 24 + r)*B_ROW_W + q;

#pragma unroll
            for (int kb = 0; kb < 4; kb++) {
                int ko = kb*8;
                uint32_t b0[4], b1[4];
                b0[0] = bh[rb0 + ko]; b1[0] = bh[rb0 + ko + 4];
                b0[1] = bh[rb1 + ko]; b1[1] = bh[rb1 + ko + 4];
                b0[2] = bh[rb2 + ko]; b1[2] = bh[rb2 + ko + 4];
                b0[3] = bh[rb3 + ko]; b1[3] = bh[rb3 + ko + 4];
#pragma unroll
                for (int g = 0; g < 4; g++) mma16(accM[g], Ah[kb], b0[g], b1[g]);
            }

            // epilogue: branchless bound update + ballot-gated rare pushes
#pragma unroll
            for (int g = 0; g < 4; g++) {
                int code0 = ch*CCH + grp*32 + g*8 + 2*q;
                float e20 = e2s[code0];
                float e21 = e2s[code0 + 1];
                float d0 = fmaf(-2.0f, accM[g][0], e20);
                float d1 = fmaf(-2.0f, accM[g][1], e21);
                float d2 = fmaf(-2.0f, accM[g][2], e20);
                float d3 = fmaf(-2.0f, accM[g][3], e21);
                bool p0 = d0 < rbm0, p1 = d1 < rbm0;
                bool p2 = d2 < rbm1, p3 = d3 < rbm1;
                rbm0 = fminf(rbm0, fminf(d0, d1) + marg0);
                rbm1 = fminf(rbm1, fminf(d2, d3) + marg1);
                if (__ballot_sync(0xffffffffu, p0 | p1 | p2 | p3)) {
                    if (p0) { int p = atomicAdd(&wq_cnt[wid], 1);
                              if (p < QCAP) wq[p] = (uint16_t)((r << 11) | code0); }
                    if (p1) { int p = atomicAdd(&wq_cnt[wid], 1);
                              if (p < QCAP) wq[p] = (uint16_t)((r << 11) | (code0 + 1)); }
                    if (p2) { int p = atomicAdd(&wq_cnt[wid], 1);
                              if (p < QCAP) wq[p] = (uint16_t)(((r + 8) << 11) | code0); }
                    if (p3) { int p = atomicAdd(&wq_cnt[wid], 1);
                              if (p < QCAP) wq[p] = (uint16_t)(((r + 8) << 11) | (code0 + 1)); }
                }
            }
        }

        // tighten bounds across the 4 q-lanes of each token
        rbm0 = fminf(rbm0, __shfl_xor_sync(0xffffffffu, rbm0, 1));
        rbm0 = fminf(rbm0, __shfl_xor_sync(0xffffffffu, rbm0, 2));
        rbm1 = fminf(rbm1, __shfl_xor_sync(0xffffffffu, rbm1, 1));
        rbm1 = fminf(rbm1, __shfl_xor_sync(0xffffffffu, rbm1, 2));

        __syncthreads();
        if (more) {
            uint32_t* dst = bw + (1 - buf)*B_TILE_W;
#pragma unroll
            for (int i = 0; i < 4; i++) {
                int idx = tid + i*256;
                int c0 = idx >> 3, w0 = (idx & 7)*4;
                *(uint4*)(dst + c0*B_ROW_W + w0) = pv[i];
            }
        }
        __syncthreads();
    }

    // ================= exact rescore of candidates =================
    __syncwarp();
    int nq = wq_cnt[wid];
    int n  = nq < QCAP ? nq : QCAP;
    for (int i = lane; i < n; i += 32) {
        uint16_t e = wq[i];
        int slot = e >> 11, c = e & 0x7FF;
        int t = tokw + slot;
        float d = rescore(cb, xsT, e2s, t, c);
        unsigned long long key = ((unsigned long long)fkey(d) << 32) | (unsigned)c;
        atomicMin(&tbl[t], key);
    }
    if (nq > QCAP) {   // overflow: exhaustive exact fallback (correctness guarantee)
        for (int s = 0; s < 16; s++) {
            int t = tokw + s;
            for (int c = lane; c < CODEBOOK; c += 32) {
                float d = rescore(cb, xsT, e2s, t, c);
                unsigned long long key = ((unsigned long long)fkey(d) << 32) | (unsigned)c;
                atomicMin(&tbl[t], key);
            }
        }
    }
    __syncthreads();

    // ---- idx write ----
    if (tid < TB) {
        int bc = (int)(tbl[tid] & 0xFFFFFFFFull);
        out[IDX_OFF + (size_t)(tok0 + tid)] = (float)bc;
    }
    __syncthreads();

    // ---- msg write + commitment-loss partial (exact fp32 x) ----
    float part = 0.0f;
    for (int f = tid; f < TB*OUT_DIM; f += NTHREADS) {
        int t = f >> 6, j = f & 63;
        int c = (int)(tbl[t] & 0xFFFFFFFFull);
        float qv = __ldg(cb + (size_t)c * OUT_DIM + j);
        float xv = xsT[j*XT_STRIDE + t];
        out[(size_t)(tok0 + t)*OUT_DIM + j] = xv + (qv - xv);
        float dd = qv - xv;
        part += dd * dd;
    }
#pragma unroll
    for (int o = 16; o > 0; o >>= 1)
        part += __shfl_down_sync(0xffffffffu, part, o);
    __shared__ float swred[8];
    if ((tid & 31) == 0) swred[tid >> 5] = part;
    __syncthreads();
    if (tid == 0) {
        float s = 0.0f;
#pragma unroll
        for (int w = 0; w < 8; w++) s += swred[w];
        g_partial[blockIdx.x] = s;
    }
}

// ---------------- deterministic loss reduction ----------------
__global__ void loss_reduce(float* __restrict__ out) {
    __shared__ float s[NBLOCKS];
    int t = threadIdx.x;
    s[t] = g_partial[t];
    __syncthreads();
    for (int o = NBLOCKS/2; o > 0; o >>= 1) {
        if (t < o) s[t] += s[t + o];
        __syncthreads();
    }
    if (t == 0) out[LOSS_OFF] = s[0] * (1.0f / (float)MSG_ELEMS);
}

extern "C" void kernel_launch(void* const* d_in, const int* in_sizes, int n_in,
                              void* d_out, int out_size)
{
    const float* obs = (const float*)d_in[0];
    const float* W1  = (const float*)d_in[1];
    const float* b1  = (const float*)d_in[2];
    const float* W2  = (const float*)d_in[3];
    const float* b2  = (const float*)d_in[4];
    const float* W3  = (const float*)d_in[5];
    const float* b3  = (const float*)d_in[6];
    const float* cb  = (const float*)d_in[7];
    float* out = (float*)d_out;

    cudaFuncSetAttribute(vq_main, cudaFuncAttributeMaxDynamicSharedMemorySize,
                         SMEM_FLOATS * (int)sizeof(float));

    prep_kernel<<<(CODEBOOK*4 + 255)/256, 256>>>(cb);
    vq_main<<<NBLOCKS, NTHREADS, SMEM_FLOATS * sizeof(float)>>>(
        obs, W1, b1, W2, b2, W3, b3, cb, out);
    loss_reduce<<<1, NBLOCKS>>>(out);
}

// round 10
// speedup vs baseline: 1.0662x; 1.0588x over previous
#include <cuda_runtime.h>
#include <cuda_fp16.h>
#include <math.h>
#include <float.h>
#include <stdint.h>

// ---------------- problem constants ----------------
#define TOKENS_TOTAL (32*2048)
#define IN_DIM   128
#define HID      64
#define OUT_DIM  64
#define CODEBOOK 2048

#define TB       128
#define NTHREADS 256
#define NBLOCKS  (TOKENS_TOTAL/TB)     // 512
#define XT_STRIDE 130
#define CCH      64                     // codes per staged chunk
#define NCH      (CODEBOOK/CCH)         // 32

// output layout: msg ++ idx(as float) ++ loss
#define MSG_ELEMS ((size_t)TOKENS_TOTAL*OUT_DIM)
#define IDX_OFF   MSG_ELEMS
#define LOSS_OFF  (MSG_ELEMS + TOKENS_TOTAL)

// ---------------- smem layout (word offsets; 1 word = 4B) ----------------
#define OFF_E2   0                      // 2048 f
#define OFF_XT   2048                   // 64 x 130 f -> end 10368
#define OFF_B    10368                  // 3 bufs x (hi 64x36 + lo 64x36) = 13824 w -> 24192
#define B_ROW_W   36                    // words per code row (32 data + 4 pad), 16B-aligned
#define B_TILE_W  (CCH*B_ROW_W)         // 2304
#define B_BUF_W   (2*B_TILE_W)          // 4608 (hi tile then lo tile)
// MLP-phase overlays (time-disjoint with B region)
#define OFF_W    10368                  // weights (<= 8192 f), MLP only
#define OFF_OBS  18560                  // obs tile / h2 (8192 f), MLP only -> 26752
#define OFF_H1   2048                   // h1 overlays XT (XT written later)
#define SMEM_FLOATS 26752               // 107008 B ; x2 CTAs fits 228KB

// packed codebook, FRAGMENT ORDER (r5-verified): [hi | lo] tiles,
// each [2048 codes][32 words], packed[c][q*8 + kb*2 + b] = orig word kb*8 + 4b + q
#define CBW 32
__device__ uint4 g_cbpack4[2 * CODEBOOK * CBW / 4];   // 512 KB
__device__ float g_e2[CODEBOOK];
__device__ float g_partial[NBLOCKS];

// ---------------- fp16 split helpers ----------------
__device__ __forceinline__ void split_h2(float x0, float x1, uint32_t& h, uint32_t& l) {
    __half h0 = __float2half_rn(x0);
    __half h1 = __float2half_rn(x1);
    float  l0 = x0 - __half2float(h0);
    float  l1 = x1 - __half2float(h1);
    __half2 hh = __halves2half2(h0, h1);
    __half2 ll = __floats2half2_rn(l0, l1);
    h = *(uint32_t*)&hh;
    l = *(uint32_t*)&ll;
}

__device__ __forceinline__ void mma16(float* c, const uint32_t* a, uint32_t b0, uint32_t b1) {
    asm volatile(
        "mma.sync.aligned.m16n8k16.row.col.f32.f16.f16.f32 "
        "{%0,%1,%2,%3}, {%4,%5,%6,%7}, {%8,%9}, {%0,%1,%2,%3};"
        : "+f"(c[0]), "+f"(c[1]), "+f"(c[2]), "+f"(c[3])
        : "r"(a[0]), "r"(a[1]), "r"(a[2]), "r"(a[3]), "r"(b0), "r"(b1));
}

// packed fp32x2 (MLP)
__device__ __forceinline__ unsigned long long dup2(float x) {
    unsigned long long r; asm("mov.b64 %0, {%1, %1};" : "=l"(r) : "f"(x)); return r;
}
__device__ __forceinline__ void ffma2(unsigned long long& d, unsigned long long a, unsigned long long b) {
    asm("fma.rn.f32x2 %0, %1, %2, %0;" : "+l"(d) : "l"(a), "l"(b));
}
__device__ __forceinline__ float lo32(unsigned long long v) { return __uint_as_float((unsigned)v); }
__device__ __forceinline__ float hi32(unsigned long long v) { return __uint_as_float((unsigned)(v >> 32)); }

// ---------------- MLP layer (proven rounds 1..9) ----------------
template<int KD, int NT, int OUTMODE, bool RELU>
__device__ __forceinline__ void mlp_layer(const float* in_s, int in_stride,
                                          const float* w_s, const float* __restrict__ b_g,
                                          float* out_s, int tid)
{
    const int jg = tid & 7;
    const int tg = tid >> 3;
    float bj[4][2];
#pragma unroll
    for (int jj = 0; jj < 4; jj++) {
        int j0 = jg*2 + 16*jj;
        bj[jj][0] = __ldg(b_g + j0);
        bj[jj][1] = __ldg(b_g + j0 + 1);
    }
    unsigned long long acc[NT][4];
#pragma unroll
    for (int it = 0; it < NT; it++)
#pragma unroll
        for (int jj = 0; jj < 4; jj++) acc[it][jj] = 0ULL;

#pragma unroll 4
    for (int k0 = 0; k0 < KD; k0 += 4) {
        float xin[NT][4];
#pragma unroll
        for (int it = 0; it < NT; it++) {
            float4 v = *(const float4*)(in_s + (tg*NT + it)*in_stride + k0);
            xin[it][0] = v.x; xin[it][1] = v.y; xin[it][2] = v.z; xin[it][3] = v.w;
        }
#pragma unroll
        for (int kk = 0; kk < 4; kk++) {
            unsigned long long wp[4];
#pragma unroll
            for (int jj = 0; jj < 4; jj++)
                wp[jj] = *(const unsigned long long*)(w_s + (k0+kk)*64 + jg*2 + 16*jj);
#pragma unroll
            for (int it = 0; it < NT; it++) {
                unsigned long long xd = dup2(xin[it][kk]);
#pragma unroll
                for (int jj = 0; jj < 4; jj++) ffma2(acc[it][jj], xd, wp[jj]);
            }
        }
    }
#pragma unroll
    for (int it = 0; it < NT; it++) {
        int t = tg*NT + it;
#pragma unroll
        for (int jj = 0; jj < 4; jj++) {
            int j0 = jg*2 + 16*jj;
            float v0 = lo32(acc[it][jj]) + bj[jj][0];
            float v1 = hi32(acc[it][jj]) + bj[jj][1];
            if (RELU) { v0 = fmaxf(v0, 0.0f); v1 = fmaxf(v1, 0.0f); }
            if (OUTMODE == 0) {
                out_s[t*64 + j0]     = v0;
                out_s[t*64 + j0 + 1] = v1;
            } else {
                out_s[j0*XT_STRIDE + t]       = v0;
                out_s[(j0 + 1)*XT_STRIDE + t] = v1;
            }
        }
    }
}

// ---------------- prep: fragment-order fp16 hi/lo pack + exact e2 (r5-verified mapping) ----------------
// 4 threads/code; thread q owns orig words w = kb*8 + 4b + q -> packed slots q*8 + kb*2 + b
__global__ void prep_kernel(const float* __restrict__ cb) {
    int gt = blockIdx.x * 256 + threadIdx.x;
    int c  = gt >> 2;
    int q  = gt & 3;
    if (c >= CODEBOOK) return;

    uint32_t hw[8], lw[8];
    float sq = 0.0f;
#pragma unroll
    for (int s = 0; s < 8; s++) {
        int kb = s >> 1, b = s & 1;
        int w  = kb*8 + 4*b + q;
        float x0 = __ldg(cb + (size_t)c*OUT_DIM + 2*w);
        float x1 = __ldg(cb + (size_t)c*OUT_DIM + 2*w + 1);
        split_h2(x0, x1, hw[s], lw[s]);
        sq += x0*x0 + x1*x1;
    }
    uint32_t* pack = (uint32_t*)g_cbpack4;
    uint32_t* hrow = pack + c*CBW + q*8;
    uint32_t* lrow = hrow + CODEBOOK*CBW;
    *(uint4*)(hrow)     = make_uint4(hw[0], hw[1], hw[2], hw[3]);
    *(uint4*)(hrow + 4) = make_uint4(hw[4], hw[5], hw[6], hw[7]);
    *(uint4*)(lrow)     = make_uint4(lw[0], lw[1], lw[2], lw[3]);
    *(uint4*)(lrow + 4) = make_uint4(lw[4], lw[5], lw[6], lw[7]);

    sq += __shfl_xor_sync(0xffffffffu, sq, 1);
    sq += __shfl_xor_sync(0xffffffffu, sq, 2);
    if (q == 0) g_e2[c] = sq;
}

// ---------------- staging: pure uint4 copy, packed-global -> smem rows of 36 words ----------------
__device__ __forceinline__ void b_ldg(int ch, int tid, uint4* v) {
    const uint4* hb = g_cbpack4 + (size_t)ch*CCH*(CBW/4);         // 512 uint4 hi
    const uint4* lb = hb + CODEBOOK*(CBW/4);                       // lo tile
    v[0] = __ldg(hb + tid);          // hi idx tid
    v[1] = __ldg(hb + tid + 256);    // hi idx tid+256
    v[2] = __ldg(lb + tid);
    v[3] = __ldg(lb + tid + 256);
}
__device__ __forceinline__ void b_sts(uint32_t* bbuf, int tid, const uint4* v) {
#pragma unroll
    for (int i = 0; i < 2; i++) {
        int idx = tid + i*256;
        int c0 = idx >> 3, sub = idx & 7;
        *(uint4*)(bbuf + c0*B_ROW_W + sub*4)            = v[i];     // hi
        *(uint4*)(bbuf + B_TILE_W + c0*B_ROW_W + sub*4) = v[i+2];   // lo
    }
}

// ---------------- fused kernel ----------------
__global__ void __launch_bounds__(NTHREADS, 2)
vq_main(const float* __restrict__ obs,
        const float* __restrict__ W1, const float* __restrict__ b1,
        const float* __restrict__ W2, const float* __restrict__ b2,
        const float* __restrict__ W3, const float* __restrict__ b3,
        const float* __restrict__ cb,
        float* __restrict__ out)
{
    extern __shared__ float sm[];
    const int tid  = threadIdx.x;
    const int wid  = tid >> 5;
    const int lane = tid & 31;
    const int r    = lane >> 2;      // 0..7
    const int q    = lane & 3;       // 0..3
    const int tok0 = blockIdx.x * TB;

    for (int i = tid; i < CODEBOOK; i += NTHREADS) sm[OFF_E2 + i] = g_e2[i];

    // ================= MLP (FFMA2, bit-identical to prior rounds) =================
    {
        const float4* w4 = (const float4*)W1;
        float4* d4 = (float4*)(sm + OFF_W);
        for (int i = tid; i < (IN_DIM*HID)/4; i += NTHREADS) d4[i] = w4[i];
    }
    for (int half = 0; half < 2; half++) {
        __syncthreads();
        const float4* o4 = (const float4*)(obs + (size_t)(tok0 + half*64) * IN_DIM);
        float4* d4 = (float4*)(sm + OFF_OBS);
        for (int i = tid; i < (64*IN_DIM)/4; i += NTHREADS) d4[i] = o4[i];
        __syncthreads();
        mlp_layer<IN_DIM, 2, 0, true>(sm + OFF_OBS, IN_DIM, sm + OFF_W, b1,
                                      sm + OFF_H1 + half*64*HID, tid);
    }
    __syncthreads();
    {
        const float4* w4 = (const float4*)W2;
        float4* d4 = (float4*)(sm + OFF_W);
        for (int i = tid; i < (HID*HID)/4; i += NTHREADS) d4[i] = w4[i];
    }
    __syncthreads();
    mlp_layer<HID, 4, 0, true>(sm + OFF_H1, HID, sm + OFF_W, b2, sm + OFF_OBS, tid);
    __syncthreads();
    {
        const float4* w4 = (const float4*)W3;
        float4* d4 = (float4*)(sm + OFF_W);
        for (int i = tid; i < (HID*OUT_DIM)/4; i += NTHREADS) d4[i] = w4[i];
    }
    __syncthreads();
    mlp_layer<HID, 4, 1, false>(sm + OFF_OBS, HID, sm + OFF_W, b3, sm + OFF_XT, tid);
    __syncthreads();

    // ========== A fragments (m16 x k64, fp16 hi/lo), built once per warp ==========
    const float* xsT = sm + OFF_XT;
    const int tokw = wid * 16;
    uint32_t Ah[4][4], Al[4][4];
#pragma unroll
    for (int kb = 0; kb < 4; kb++) {
        int k0 = kb*16;
        const float* x0 = xsT + tokw;
        float v00 = x0[(k0 + 2*q    )*XT_STRIDE + r];
        float v01 = x0[(k0 + 2*q + 1)*XT_STRIDE + r];
        float v10 = x0[(k0 + 2*q    )*XT_STRIDE + r + 8];
        float v11 = x0[(k0 + 2*q + 1)*XT_STRIDE + r + 8];
        float v20 = x0[(k0 + 2*q + 8)*XT_STRIDE + r];
        float v21 = x0[(k0 + 2*q + 9)*XT_STRIDE + r];
        float v30 = x0[(k0 + 2*q + 8)*XT_STRIDE + r + 8];
        float v31 = x0[(k0 + 2*q + 9)*XT_STRIDE + r + 8];
        split_h2(v00, v01, Ah[kb][0], Al[kb][0]);
        split_h2(v10, v11, Ah[kb][1], Al[kb][1]);
        split_h2(v20, v21, Ah[kb][2], Al[kb][2]);
        split_h2(v30, v31, Ah[kb][3], Al[kb][3]);
    }

    // ================= VQ: fp16 m16n8k16 3-term, LDS.128 B feed, triple buffer =================
    float best_d0 = FLT_MAX, best_d1 = FLT_MAX;
    int   best_c0 = 0,       best_c1 = 0;

    uint32_t* bw = (uint32_t*)(sm + OFF_B);

    // prologue: stage chunk 0 into buf 0
    {
        uint4 st[4];
        b_ldg(0, tid, st);
        b_sts(bw, tid, st);
        __syncthreads();
    }

    for (int ch = 0; ch < NCH; ch++) {
        const int buf = ch % 3;
        uint4 pv[4];
        const bool more = (ch + 1 < NCH);
        if (more) b_ldg(ch + 1, tid, pv);

        const uint32_t* bb = bw + buf*B_BUF_W;

#pragma unroll
        for (int grp = 0; grp < 2; grp++) {
#pragma unroll
            for (int gp = 0; gp < 2; gp++) {
                // rows: g = 2gp (a), 2gp+1 (b)
                const uint32_t* pa = bb + (grp*32 + gp*16 + r)*B_ROW_W + q*8;
                const uint32_t* pb = pa + 8*B_ROW_W;
                uint4 h0a = *(const uint4*)(pa);
                uint4 h1a = *(const uint4*)(pa + 4);
                uint4 h0b = *(const uint4*)(pb);
                uint4 h1b = *(const uint4*)(pb + 4);
                uint4 l0a = *(const uint4*)(pa + B_TILE_W);
                uint4 l1a = *(const uint4*)(pa + B_TILE_W + 4);
                uint4 l0b = *(const uint4*)(pb + B_TILE_W);
                uint4 l1b = *(const uint4*)(pb + B_TILE_W + 4);

                float aMa[4]={0,0,0,0}, aMb[4]={0,0,0,0};
                float aCa[4]={0,0,0,0}, aCb[4]={0,0,0,0};
                float aDa[4]={0,0,0,0}, aDb[4]={0,0,0,0};

                // kb 0..3 per accumulator chain (same order as r6 -> bit-identical)
                mma16(aMa, Ah[0], h0a.x, h0a.y);  mma16(aMb, Ah[0], h0b.x, h0b.y);
                mma16(aCa, Ah[0], l0a.x, l0a.y);  mma16(aCb, Ah[0], l0b.x, l0b.y);
                mma16(aDa, Al[0], h0a.x, h0a.y);  mma16(aDb, Al[0], h0b.x, h0b.y);

                mma16(aMa, Ah[1], h0a.z, h0a.w);  mma16(aMb, Ah[1], h0b.z, h0b.w);
                mma16(aCa, Ah[1], l0a.z, l0a.w);  mma16(aCb, Ah[1], l0b.z, l0b.w);
                mma16(aDa, Al[1], h0a.z, h0a.w);  mma16(aDb, Al[1], h0b.z, h0b.w);

                mma16(aMa, Ah[2], h1a.x, h1a.y);  mma16(aMb, Ah[2], h1b.x, h1b.y);
                mma16(aCa, Ah[2], l1a.x, l1a.y);  mma16(aCb, Ah[2], l1b.x, l1b.y);
                mma16(aDa, Al[2], h1a.x, h1a.y);  mma16(aDb, Al[2], h1b.x, h1b.y);

                mma16(aMa, Ah[3], h1a.z, h1a.w);  mma16(aMb, Ah[3], h1b.z, h1b.w);
                mma16(aCa, Ah[3], l1a.z, l1a.w);  mma16(aCb, Ah[3], l1b.z, l1b.w);
                mma16(aDa, Al[3], h1a.z, h1a.w);  mma16(aDb, Al[3], h1b.z, h1b.w);

                // epilogue, codes ascending: g=2gp then g=2gp+1
#pragma unroll
                for (int half = 0; half < 2; half++) {
                    const float* aM = half ? aMb : aMa;
                    const float* aC = half ? aCb : aCa;
                    const float* aD = half ? aDb : aDa;
                    int code0 = ch*CCH + grp*32 + (gp*2 + half)*8 + 2*q;
                    float e20 = sm[OFF_E2 + code0];
                    float e21 = sm[OFF_E2 + code0 + 1];
                    float s0 = aM[0] + aC[0] + aD[0];
                    float s1 = aM[1] + aC[1] + aD[1];
                    float s2 = aM[2] + aC[2] + aD[2];
                    float s3 = aM[3] + aC[3] + aD[3];
                    float d0 = fmaf(-2.0f, s0, e20);
                    float d1 = fmaf(-2.0f, s1, e21);
                    float d2 = fmaf(-2.0f, s2, e20);
                    float d3 = fmaf(-2.0f, s3, e21);
                    if (d0 < best_d0) { best_d0 = d0; best_c0 = code0; }
                    if (d1 < best_d0) { best_d0 = d1; best_c0 = code0 + 1; }
                    if (d2 < best_d1) { best_d1 = d2; best_c1 = code0; }
                    if (d3 < best_d1) { best_d1 = d3; best_c1 = code0 + 1; }
                }
            }
        }

        if (more) b_sts(bw + ((ch + 1) % 3)*B_BUF_W, tid, pv);
        __syncthreads();   // single barrier: publishes buf(ch+1), retires buf(ch-1)
    }

    // ---- cross-lane argmin (4 lanes per token row), tie-break: smaller code ----
#pragma unroll
    for (int m = 1; m <= 2; m <<= 1) {
        float od0 = __shfl_xor_sync(0xffffffffu, best_d0, m);
        int   oc0 = __shfl_xor_sync(0xffffffffu, best_c0, m);
        float od1 = __shfl_xor_sync(0xffffffffu, best_d1, m);
        int   oc1 = __shfl_xor_sync(0xffffffffu, best_c1, m);
        if (od0 < best_d0 || (od0 == best_d0 && oc0 < best_c0)) { best_d0 = od0; best_c0 = oc0; }
        if (od1 < best_d1 || (od1 == best_d1 && oc1 < best_c1)) { best_d1 = od1; best_c1 = oc1; }
    }

    int* sIdx = (int*)(sm + OFF_B);      // B region dead now
    if (q == 0) {
        int t0 = tokw + r;
        sIdx[t0]     = best_c0;
        sIdx[t0 + 8] = best_c1;
        out[IDX_OFF + (size_t)(tok0 + t0)]     = (float)best_c0;
        out[IDX_OFF + (size_t)(tok0 + t0 + 8)] = (float)best_c1;
    }
    __syncthreads();

    // ---- msg write + commitment-loss partial (exact fp32 x) ----
    float part = 0.0f;
    for (int f = tid; f < TB*OUT_DIM; f += NTHREADS) {
        int t = f >> 6, j = f & 63;
        int c = sIdx[t];
        float qv = __ldg(cb + (size_t)c * OUT_DIM + j);
        float xv = xsT[j*XT_STRIDE + t];
        out[(size_t)(tok0 + t)*OUT_DIM + j] = xv + (qv - xv);
        float dd = qv - xv;
        part += dd * dd;
    }
#pragma unroll
    for (int o = 16; o > 0; o >>= 1)
        part += __shfl_down_sync(0xffffffffu, part, o);
    __shared__ float swred[8];
    if ((tid & 31) == 0) swred[tid >> 5] = part;
    __syncthreads();
    if (tid == 0) {
        float s = 0.0f;
#pragma unroll
        for (int w = 0; w < 8; w++) s += swred[w];
        g_partial[blockIdx.x] = s;
    }
}

// ---------------- deterministic loss reduction ----------------
__global__ void loss_reduce(float* __restrict__ out) {
    __shared__ float s[NBLOCKS];
    int t = threadIdx.x;
    s[t] = g_partial[t];
    __syncthreads();
    for (int o = NBLOCKS/2; o > 0; o >>= 1) {
        if (t < o) s[t] += s[t + o];
        __syncthreads();
    }
    if (t == 0) out[LOSS_OFF] = s[0] * (1.0f / (float)MSG_ELEMS);
}

extern "C" void kernel_launch(void* const* d_in, const int* in_sizes, int n_in,
                              void* d_out, int out_size)
{
    const float* obs = (const float*)d_in[0];
    const float* W1  = (const float*)d_in[1];
    const float* b1  = (const float*)d_in[2];
    const float* W2  = (const float*)d_in[3];
    const float* b2  = (const float*)d_in[4];
    const float* W3  = (const float*)d_in[5];
    const float* b3  = (const float*)d_in[6];
    const float* cb  = (const float*)d_in[7];
    float* out = (float*)d_out;

    cudaFuncSetAttribute(vq_main, cudaFuncAttributeMaxDynamicSharedMemorySize,
                         SMEM_FLOATS * (int)sizeof(float));

    prep_kernel<<<(CODEBOOK*4 + 255)/256, 256>>>(cb);
    vq_main<<<NBLOCKS, NTHREADS, SMEM_FLOATS * sizeof(float)>>>(
        obs, W1, b1, W2, b2, W3, b3, cb, out);
    loss_reduce<<<1, NBLOCKS>>>(out);
}